// round 11
// baseline (speedup 1.0000x reference)
#include <cuda_runtime.h>
#include <cuda_bf16.h>
#include <cstdint>

#define N_ROWS 2048
#define W_FLAT (128*128*3)
#define MAX_TILES 256
#define P_TOT 18432            // 2048*(1+3+5)

// ---------------- persistent device scratch (static, alloc-free) -----------
__device__ __nv_bfloat16 g_XH[P_TOT * 128];      // X transposed [p][m], hi
__device__ __nv_bfloat16 g_XL[P_TOT * 128];      // lo
__device__ __nv_bfloat16 g_WH[96 * 128 * 128];   // W^T per (g,irW): [o][m], hi (alpha folded)
__device__ __nv_bfloat16 g_WL[96 * 128 * 128];   // lo

// ---------------- tile list ----------------
__device__ int g_t_p0[MAX_TILES];
__device__ int g_t_pcnt[MAX_TILES];
__device__ int g_t_seg[MAX_TILES];
__device__ int g_t_irr[MAX_TILES];
__device__ int g_ntiles;

__global__ void build_tiles_kernel(const int* __restrict__ repeats) {
    int t = threadIdx.x;
    int cnt = repeats[t];
    int inc = cnt;
    #pragma unroll
    for (int off = 1; off < 32; off <<= 1) {
        int v = __shfl_up_sync(0xFFFFFFFFu, inc, off);
        if (t >= off) inc += v;
    }
    int start = inc - cnt;

    const int Ds[3] = {5, 3, 1};       // heavy first (ir code 0,1,2)
    const int pb[3] = {8192, 2048, 0}; // p-base in concat X layout [D1|D3|D5]
    int base = 0;
    #pragma unroll
    for (int ir = 0; ir < 3; ir++) {
        int D = Ds[ir];
        int pc = cnt * D;
        int nt = (pc + 127) >> 7;
        int ti = nt;
        #pragma unroll
        for (int off = 1; off < 32; off <<= 1) {
            int v = __shfl_up_sync(0xFFFFFFFFu, ti, off);
            if (t >= off) ti += v;
        }
        int ts = ti - nt;
        for (int k = 0; k < nt; k++) {
            int idx = base + ts + k;
            g_t_p0[idx]   = pb[ir] + start * D + k * 128;
            int rem = pc - k * 128;
            g_t_pcnt[idx] = rem < 128 ? rem : 128;
            g_t_seg[idx]  = t;
            g_t_irr[idx]  = ir;
        }
        base += __shfl_sync(0xFFFFFFFFu, ti, 31);
    }
    if (t == 0) g_ntiles = base;
}

// ---------------- prep: W -> bf16 hi/lo, transposed, alpha folded ----------
__global__ void prep_w_kernel(const float* __restrict__ w) {
    __shared__ __nv_bfloat16 SH[32 * 128];
    __shared__ __nv_bfloat16 SL[32 * 128];
    int g = blockIdx.x, irW = blockIdx.y;
    const float* src = w + (size_t)g * W_FLAT + irW * 16384;
    __nv_bfloat16* dH = g_WH + ((size_t)g * 3 + irW) * 16384;
    __nv_bfloat16* dL = g_WL + ((size_t)g * 3 + irW) * 16384;

    for (int mc = 0; mc < 128; mc += 32) {
        for (int idx = threadIdx.x; idx < 4096; idx += 256) {
            int mm = idx >> 7, o = idx & 127;
            float v = src[(size_t)(mc + mm) * 128 + o] * 0.015625f; // alpha
            __nv_bfloat16 h = __float2bfloat16(v);
            __nv_bfloat16 l = __float2bfloat16(v - __bfloat162float(h));
            SH[mm * 128 + o] = h;
            SL[mm * 128 + o] = l;
        }
        __syncthreads();
        for (int idx = threadIdx.x; idx < 4096; idx += 256) {
            int o = idx >> 5, mm = idx & 31;
            dH[(size_t)o * 128 + mc + mm] = SH[mm * 128 + o];
            dL[(size_t)o * 128 + mc + mm] = SL[mm * 128 + o];
        }
        __syncthreads();
    }
}

// ---------------- prep: X -> bf16 hi/lo, [p][m] ----------------------------
__global__ void prep_x_kernel(const float* __restrict__ x0,
                              const float* __restrict__ x1,
                              const float* __restrict__ x2) {
    __shared__ float buf[16 * 128 * 5];
    int sel = blockIdx.y;
    const float* x;
    int D, pbase;
    if (sel == 0)      { x = x0; D = 1; pbase = 0; }
    else if (sel == 1) { x = x1; D = 3; pbase = 2048; }
    else               { x = x2; D = 5; pbase = 8192; }

    int n0 = blockIdx.x * 16;
    int tot = 16 * 128 * D;
    const float* src = x + (size_t)n0 * 128 * D;
    for (int idx = threadIdx.x; idx < tot; idx += 256) buf[idx] = src[idx];
    __syncthreads();
    for (int idx = threadIdx.x; idx < tot; idx += 256) {
        int nl  = idx / (128 * D);
        int rem = idx - nl * (128 * D);
        int i = rem >> 7;
        int m = rem & 127;
        float v = buf[nl * 128 * D + m * D + i];
        __nv_bfloat16 h = __float2bfloat16(v);
        __nv_bfloat16 l = __float2bfloat16(v - __bfloat162float(h));
        size_t p = ((size_t)(pbase + (n0 + nl) * D + i)) * 128 + m;
        g_XH[p] = h;
        g_XL[p] = l;
    }
}

// ---------------- mma / ldmatrix helpers ----------------
__device__ __forceinline__ uint32_t smem_u32(const void* p) {
    uint32_t a;
    asm("{ .reg .u64 t; cvta.to.shared.u64 t, %1; cvt.u32.u64 %0, t; }"
        : "=r"(a) : "l"(p));
    return a;
}
#define LDSM4(r0, r1, r2, r3, a) \
    asm volatile("ldmatrix.sync.aligned.m8n8.x4.shared.b16 {%0,%1,%2,%3}, [%4];" \
                 : "=r"(r0), "=r"(r1), "=r"(r2), "=r"(r3) : "r"(a))
__device__ __forceinline__ void mma16(float* d, uint32_t a0, uint32_t a1,
                                      uint32_t a2, uint32_t a3,
                                      uint32_t b0, uint32_t b1) {
    asm volatile(
        "mma.sync.aligned.m16n8k16.row.col.f32.bf16.bf16.f32 "
        "{%0,%1,%2,%3},{%4,%5,%6,%7},{%8,%9},{%0,%1,%2,%3};"
        : "+f"(d[0]), "+f"(d[1]), "+f"(d[2]), "+f"(d[3])
        : "r"(a0), "r"(a1), "r"(a2), "r"(a3), "r"(b0), "r"(b1));
}

// smem: AH[128][128B] AL BH BL = 64 KB, XOR-swizzled 16B chunks
#define SMEM_BYTES 65536

// ---------------------------------------------------------------------------
// One 128x128 tile, K=128 in 2 chunks of 64. 8 warps: warp tile 32x64.
// 3-term bf16: hh + lo*hi + hi*lo. alpha already folded into W.
// ---------------------------------------------------------------------------
template <int D>
__device__ __forceinline__ void body(float* __restrict__ out, char* smem,
                                     int p0, int pcnt, int g, int irW,
                                     int pbase) {
    const int tid  = threadIdx.x;
    const int wid  = tid >> 5;
    const int lane = tid & 31;
    const int wr   = wid & 3;
    const int wc   = wid >> 2;
    const uint32_t sbase = smem_u32(smem);
    const size_t wb = ((size_t)g * 3 + irW) * 16384;

    float acc[64];
    #pragma unroll
    for (int i = 0; i < 64; i++) acc[i] = 0.0f;

    for (int ch = 0; ch < 2; ch++) {
        const int kc = ch * 64;
        if (ch) __syncthreads();

        // ---- stage: 4096 x 16B chunks (AH,AL,BH,BL), pure copies ----
        #pragma unroll
        for (int it = 0; it < 16; it++) {
            int id  = tid + it * 256;
            int sel = id >> 10;          // constant per it
            int r   = (id >> 3) & 127;
            int c   = id & 7;
            const __nv_bfloat16* src;
            if (sel == 0)
                src = g_XH + (size_t)(p0 + (r < pcnt ? r : 0)) * 128 + kc + c * 8;
            else if (sel == 1)
                src = g_XL + (size_t)(p0 + (r < pcnt ? r : 0)) * 128 + kc + c * 8;
            else if (sel == 2)
                src = g_WH + wb + (size_t)r * 128 + kc + c * 8;
            else
                src = g_WL + wb + (size_t)r * 128 + kc + c * 8;
            uint4 v = *(const uint4*)src;
            *(uint4*)(smem + sel * 16384 + r * 128 + ((c ^ (r & 7)) << 4)) = v;
        }
        __syncthreads();

        const uint32_t sAH = sbase, sAL = sbase + 16384;
        const uint32_t sBH = sbase + 32768, sBL = sbase + 49152;

        #pragma unroll
        for (int ks = 0; ks < 4; ks++) {
            uint32_t aH[2][4], aL[2][4];
            #pragma unroll
            for (int mt = 0; mt < 2; mt++) {
                int r = wr * 32 + mt * 16 + (lane & 15);
                int c = ks * 2 + (lane >> 4);
                uint32_t off = r * 128 + ((c ^ (r & 7)) << 4);
                LDSM4(aH[mt][0], aH[mt][1], aH[mt][2], aH[mt][3], sAH + off);
                LDSM4(aL[mt][0], aL[mt][1], aL[mt][2], aL[mt][3], sAL + off);
            }
            #pragma unroll
            for (int ntp = 0; ntp < 4; ntp++) {
                int r = wc * 64 + ntp * 16 + (lane & 7) + ((lane >> 4) << 3);
                int c = ks * 2 + ((lane >> 3) & 1);
                uint32_t off = r * 128 + ((c ^ (r & 7)) << 4);
                uint32_t bh[4], bl[4];
                LDSM4(bh[0], bh[1], bh[2], bh[3], sBH + off);
                LDSM4(bl[0], bl[1], bl[2], bl[3], sBL + off);
                #pragma unroll
                for (int mt = 0; mt < 2; mt++) {
                    float* d0 = acc + mt * 32 + (ntp * 2) * 4;
                    float* d1 = acc + mt * 32 + (ntp * 2 + 1) * 4;
                    mma16(d0, aH[mt][0], aH[mt][1], aH[mt][2], aH[mt][3], bh[0], bh[1]);
                    mma16(d1, aH[mt][0], aH[mt][1], aH[mt][2], aH[mt][3], bh[2], bh[3]);
                    mma16(d0, aL[mt][0], aL[mt][1], aL[mt][2], aL[mt][3], bh[0], bh[1]);
                    mma16(d1, aL[mt][0], aL[mt][1], aL[mt][2], aL[mt][3], bh[2], bh[3]);
                    mma16(d0, aH[mt][0], aH[mt][1], aH[mt][2], aH[mt][3], bl[0], bl[1]);
                    mma16(d1, aH[mt][0], aH[mt][1], aH[mt][2], aH[mt][3], bl[2], bl[3]);
                }
            }
        }
    }

    // ---- epilogue: regs -> gmem (alpha already in W) ----
    const int p0loc = p0 - pbase;
    #pragma unroll
    for (int mt = 0; mt < 2; mt++) {
        #pragma unroll
        for (int h = 0; h < 2; h++) {
            int row = wr * 32 + mt * 16 + (lane >> 2) + h * 8;
            if (row < pcnt) {
                int p = p0loc + row;
                int n = p / D;
                int i = p - n * D;
                float* ob = out + (size_t)n * 128 * D + i;
                #pragma unroll
                for (int nt = 0; nt < 8; nt++) {
                    int o = wc * 64 + nt * 8 + (lane & 3) * 2;
                    ob[(size_t)o * D]       = acc[mt * 32 + nt * 4 + h * 2 + 0];
                    ob[(size_t)(o + 1) * D] = acc[mt * 32 + nt * 4 + h * 2 + 1];
                }
            }
        }
    }
}

// ---------------------------------------------------------------------------
__global__ __launch_bounds__(256, 2)
void irreps_mma_kernel(float* __restrict__ out) {
    extern __shared__ char smem[];
    int tile = blockIdx.x;
    if (tile >= g_ntiles) return;

    const int p0   = g_t_p0[tile];
    const int pcnt = g_t_pcnt[tile];
    const int g    = g_t_seg[tile];
    const int ir   = g_t_irr[tile];

    if (ir == 0)        // D=5
        body<5>(out + (size_t)2048 * 128 * 4, smem, p0, pcnt, g, 2, 8192);
    else if (ir == 1)   // D=3
        body<3>(out + (size_t)2048 * 128 * 1, smem, p0, pcnt, g, 1, 2048);
    else                // D=1
        body<1>(out, smem, p0, pcnt, g, 0, 0);
}

// ---------------------------------------------------------------------------
extern "C" void kernel_launch(void* const* d_in, const int* in_sizes, int n_in,
                              void* d_out, int out_size) {
    const float* x0 = (const float*)d_in[0];   // (2048,128,1)
    const float* x1 = (const float*)d_in[1];   // (2048,128,3)
    const float* x2 = (const float*)d_in[2];   // (2048,128,5)
    const float* w  = (const float*)d_in[3];   // (32, 49152)
    const int*   rp = (const int*)d_in[4];     // (32,)
    float* out = (float*)d_out;

    cudaFuncSetAttribute(irreps_mma_kernel,
                         cudaFuncAttributeMaxDynamicSharedMemorySize, SMEM_BYTES);

    build_tiles_kernel<<<1, 32>>>(rp);
    prep_w_kernel<<<dim3(32, 3), 256>>>(w);
    prep_x_kernel<<<dim3(128, 3), 256>>>(x0, x1, x2);
    irreps_mma_kernel<<<MAX_TILES, 256, SMEM_BYTES>>>(out);
}

// round 12
// speedup vs baseline: 1.9271x; 1.9271x over previous
#include <cuda_runtime.h>
#include <cuda_bf16.h>
#include <cstdint>

#define N_ROWS 2048
#define W_FLAT (128*128*3)
#define MAX_TILES 256
#define P_TOT 18432            // 2048*(1+3+5)

// ---------------- persistent device scratch (static, alloc-free) -----------
__device__ __nv_bfloat16 g_XH[P_TOT * 128];      // X transposed [p][m], hi
__device__ __nv_bfloat16 g_XL[P_TOT * 128];      // lo
__device__ __nv_bfloat16 g_WH[96 * 128 * 128];   // W^T per (g,irW): [o][m], hi (alpha folded)
__device__ __nv_bfloat16 g_WL[96 * 128 * 128];   // lo

// ---------------- tile list ----------------
__device__ int g_t_p0[MAX_TILES];
__device__ int g_t_pcnt[MAX_TILES];
__device__ int g_t_seg[MAX_TILES];
__device__ int g_t_irr[MAX_TILES];
__device__ int g_ntiles;

// ---------------------------------------------------------------------------
// Combined prep kernel:
//   blocks [0,96)    : W -> bf16 hi/lo, transposed [o][m], alpha folded
//   blocks [96,480)  : X -> bf16 hi/lo, [p][m]
//   block  480       : tile list build (warp 0)
// ---------------------------------------------------------------------------
__global__ __launch_bounds__(256)
void prep_kernel(const float* __restrict__ w,
                 const float* __restrict__ x0,
                 const float* __restrict__ x1,
                 const float* __restrict__ x2,
                 const int* __restrict__ repeats) {
    __shared__ float sbuf[16 * 128 * 5];   // 40 KB, aliased per role
    const int b   = blockIdx.x;
    const int tid = threadIdx.x;

    if (b < 96) {
        // ---------------- W prep ----------------
        const int g = b / 3, irW = b % 3;
        __nv_bfloat16* SH = (__nv_bfloat16*)sbuf;      // [32][130] padded
        __nv_bfloat16* SL = SH + 32 * 130;
        const float* src = w + (size_t)g * W_FLAT + irW * 16384;
        __nv_bfloat16* dH = g_WH + ((size_t)g * 3 + irW) * 16384;
        __nv_bfloat16* dL = g_WL + ((size_t)g * 3 + irW) * 16384;

        for (int mc = 0; mc < 128; mc += 32) {
            for (int idx = tid; idx < 4096; idx += 256) {
                int mm = idx >> 7, o = idx & 127;
                float v = src[(size_t)(mc + mm) * 128 + o] * 0.015625f;
                __nv_bfloat16 h = __float2bfloat16(v);
                __nv_bfloat16 l = __float2bfloat16(v - __bfloat162float(h));
                SH[mm * 130 + o] = h;
                SL[mm * 130 + o] = l;
            }
            __syncthreads();
            for (int idx = tid; idx < 2048; idx += 256) {
                int o = idx >> 4, mq = idx & 15;        // mm pair
                uint32_t ph, pl;
                __nv_bfloat16 h0 = SH[(2 * mq) * 130 + o];
                __nv_bfloat16 h1 = SH[(2 * mq + 1) * 130 + o];
                __nv_bfloat16 l0 = SL[(2 * mq) * 130 + o];
                __nv_bfloat16 l1 = SL[(2 * mq + 1) * 130 + o];
                ph = (uint32_t)*(uint16_t*)&h0 | ((uint32_t)*(uint16_t*)&h1 << 16);
                pl = (uint32_t)*(uint16_t*)&l0 | ((uint32_t)*(uint16_t*)&l1 << 16);
                *(uint32_t*)(dH + (size_t)o * 128 + mc + 2 * mq) = ph;
                *(uint32_t*)(dL + (size_t)o * 128 + mc + 2 * mq) = pl;
            }
            __syncthreads();
        }
    } else if (b < 480) {
        // ---------------- X prep ----------------
        const int xb = b - 96;
        const int sel = xb >> 7;
        const int n0 = (xb & 127) * 16;
        const float* x;
        int D, pbase;
        if (sel == 0)      { x = x0; D = 1; pbase = 0; }
        else if (sel == 1) { x = x1; D = 3; pbase = 2048; }
        else               { x = x2; D = 5; pbase = 8192; }

        const int tot = 16 * 128 * D;
        const float4* src4 = (const float4*)(x + (size_t)n0 * 128 * D);
        float4* buf4 = (float4*)sbuf;
        for (int idx = tid; idx < tot / 4; idx += 256) buf4[idx] = src4[idx];
        __syncthreads();

        const int tot2 = 16 * 64 * D;      // (nl, i, m2)
        for (int idx = tid; idx < tot2; idx += 256) {
            int nl  = idx / (64 * D);
            int rem = idx - nl * (64 * D);
            int i  = rem >> 6;
            int m2 = rem & 63;
            float f0 = sbuf[nl * 128 * D + (2 * m2) * D + i];
            float f1 = sbuf[nl * 128 * D + (2 * m2 + 1) * D + i];
            __nv_bfloat16 h0 = __float2bfloat16(f0);
            __nv_bfloat16 l0 = __float2bfloat16(f0 - __bfloat162float(h0));
            __nv_bfloat16 h1 = __float2bfloat16(f1);
            __nv_bfloat16 l1 = __float2bfloat16(f1 - __bfloat162float(h1));
            size_t p = (size_t)(pbase + (n0 + nl) * D + i);
            uint32_t ph = (uint32_t)*(uint16_t*)&h0 | ((uint32_t)*(uint16_t*)&h1 << 16);
            uint32_t pl = (uint32_t)*(uint16_t*)&l0 | ((uint32_t)*(uint16_t*)&l1 << 16);
            *(uint32_t*)(g_XH + p * 128 + 2 * m2) = ph;
            *(uint32_t*)(g_XL + p * 128 + 2 * m2) = pl;
        }
    } else if (tid < 32) {
        // ---------------- tile list ----------------
        int t = tid;
        int cnt = repeats[t];
        int inc = cnt;
        #pragma unroll
        for (int off = 1; off < 32; off <<= 1) {
            int v = __shfl_up_sync(0xFFFFFFFFu, inc, off);
            if (t >= off) inc += v;
        }
        int start = inc - cnt;
        const int Ds[3] = {5, 3, 1};
        const int pb[3] = {8192, 2048, 0};
        int base = 0;
        #pragma unroll
        for (int ir = 0; ir < 3; ir++) {
            int D = Ds[ir];
            int pc = cnt * D;
            int nt = (pc + 127) >> 7;
            int ti = nt;
            #pragma unroll
            for (int off = 1; off < 32; off <<= 1) {
                int v = __shfl_up_sync(0xFFFFFFFFu, ti, off);
                if (t >= off) ti += v;
            }
            int ts = ti - nt;
            for (int k = 0; k < nt; k++) {
                int idx = base + ts + k;
                g_t_p0[idx]   = pb[ir] + start * D + k * 128;
                int rem = pc - k * 128;
                g_t_pcnt[idx] = rem < 128 ? rem : 128;
                g_t_seg[idx]  = t;
                g_t_irr[idx]  = ir;
            }
            base += __shfl_sync(0xFFFFFFFFu, ti, 31);
        }
        if (t == 0) g_ntiles = base;
    }
}

// ---------------- mma / ldmatrix helpers ----------------
__device__ __forceinline__ uint32_t smem_u32(const void* p) {
    uint32_t a;
    asm("{ .reg .u64 t; cvta.to.shared.u64 t, %1; cvt.u32.u64 %0, t; }"
        : "=r"(a) : "l"(p));
    return a;
}
#define LDSM4(r0, r1, r2, r3, a) \
    asm volatile("ldmatrix.sync.aligned.m8n8.x4.shared.b16 {%0,%1,%2,%3}, [%4];" \
                 : "=r"(r0), "=r"(r1), "=r"(r2), "=r"(r3) : "r"(a))
__device__ __forceinline__ void mma16(float* d, uint32_t a0, uint32_t a1,
                                      uint32_t a2, uint32_t a3,
                                      uint32_t b0, uint32_t b1) {
    asm volatile(
        "mma.sync.aligned.m16n8k16.row.col.f32.bf16.bf16.f32 "
        "{%0,%1,%2,%3},{%4,%5,%6,%7},{%8,%9},{%0,%1,%2,%3};"
        : "+f"(d[0]), "+f"(d[1]), "+f"(d[2]), "+f"(d[3])
        : "r"(a0), "r"(a1), "r"(a2), "r"(a3), "r"(b0), "r"(b1));
}
#define CP16(doff, src) \
    asm volatile("cp.async.cg.shared.global [%0], [%1], 16;" :: "r"(doff), "l"(src))
#define CP_COMMIT() asm volatile("cp.async.commit_group;")
#define CP_WAIT1()  asm volatile("cp.async.wait_group 1;")
#define CP_WAIT0()  asm volatile("cp.async.wait_group 0;")

// smem: 2 buffers x (AH|AL|BH|BL each 128 rows x 64B) = 2 x 32KB = 64KB
#define BUF_BYTES 32768
#define SMEM_BYTES (2 * BUF_BYTES)

// swizzled row offset inside a plane (64B rows, 16B chunks)
__device__ __forceinline__ uint32_t swoff(int r, int cq) {
    return (uint32_t)(r * 64 + ((cq ^ ((r >> 1) & 3)) << 4));
}

// ---------------------------------------------------------------------------
// One 128x128 tile, K=128 in 4 chunks of 32, cp.async double-buffered.
// 8 warps: warp tile 32x64. 3-term bf16: hh + lo*hi + hi*lo (alpha in W).
// ---------------------------------------------------------------------------
template <int D>
__device__ __forceinline__ void body(float* __restrict__ out, char* smem,
                                     int p0, int pcnt, int g, int irW,
                                     int pbase) {
    const int tid  = threadIdx.x;
    const int wid  = tid >> 5;
    const int lane = tid & 31;
    const int wr   = wid & 3;
    const int wc   = wid >> 2;
    const uint32_t sbase = smem_u32(smem);
    const size_t wb = ((size_t)g * 3 + irW) * 16384;

    float acc[64];
    #pragma unroll
    for (int i = 0; i < 64; i++) acc[i] = 0.0f;

    auto issue = [&](int c, int bsel) {
        const int kc = c * 32;
        #pragma unroll
        for (int it = 0; it < 8; it++) {
            int id  = tid + it * 256;
            int sel = id >> 9;              // uniform per it
            int r   = (id >> 2) & 127;
            int cq  = id & 3;
            int rr  = (sel < 2) ? (r < pcnt ? r : 0) : r;
            const __nv_bfloat16* src;
            if (sel == 0)      src = g_XH + (size_t)(p0 + rr) * 128 + kc + cq * 8;
            else if (sel == 1) src = g_XL + (size_t)(p0 + rr) * 128 + kc + cq * 8;
            else if (sel == 2) src = g_WH + wb + (size_t)r * 128 + kc + cq * 8;
            else               src = g_WL + wb + (size_t)r * 128 + kc + cq * 8;
            uint32_t doff = sbase + bsel * BUF_BYTES + sel * 8192 + swoff(r, cq);
            CP16(doff, src);
        }
        CP_COMMIT();
    };

    issue(0, 0);
    issue(1, 1);

    for (int c = 0; c < 4; c++) {
        if (c < 3) CP_WAIT1(); else CP_WAIT0();
        __syncthreads();

        const uint32_t sA = sbase + (c & 1) * BUF_BYTES;
        #pragma unroll
        for (int k16 = 0; k16 < 2; k16++) {
            uint32_t aH[2][4], aL[2][4];
            #pragma unroll
            for (int mt = 0; mt < 2; mt++) {
                int r  = wr * 32 + mt * 16 + (lane & 15);
                int cq = k16 * 2 + (lane >> 4);
                uint32_t off = swoff(r, cq);
                LDSM4(aH[mt][0], aH[mt][1], aH[mt][2], aH[mt][3], sA + off);
                LDSM4(aL[mt][0], aL[mt][1], aL[mt][2], aL[mt][3], sA + 8192 + off);
            }
            #pragma unroll
            for (int ntp = 0; ntp < 4; ntp++) {
                int r  = wc * 64 + ntp * 16 + (lane & 7) + ((lane >> 4) << 3);
                int cq = k16 * 2 + ((lane >> 3) & 1);
                uint32_t off = swoff(r, cq);
                uint32_t bh[4], bl[4];
                LDSM4(bh[0], bh[1], bh[2], bh[3], sA + 16384 + off);
                LDSM4(bl[0], bl[1], bl[2], bl[3], sA + 24576 + off);
                #pragma unroll
                for (int mt = 0; mt < 2; mt++) {
                    float* d0 = acc + mt * 32 + (ntp * 2) * 4;
                    float* d1 = acc + mt * 32 + (ntp * 2 + 1) * 4;
                    mma16(d0, aH[mt][0], aH[mt][1], aH[mt][2], aH[mt][3], bh[0], bh[1]);
                    mma16(d1, aH[mt][0], aH[mt][1], aH[mt][2], aH[mt][3], bh[2], bh[3]);
                    mma16(d0, aL[mt][0], aL[mt][1], aL[mt][2], aL[mt][3], bh[0], bh[1]);
                    mma16(d1, aL[mt][0], aL[mt][1], aL[mt][2], aL[mt][3], bh[2], bh[3]);
                    mma16(d0, aH[mt][0], aH[mt][1], aH[mt][2], aH[mt][3], bl[0], bl[1]);
                    mma16(d1, aH[mt][0], aH[mt][1], aH[mt][2], aH[mt][3], bl[2], bl[3]);
                }
            }
        }

        __syncthreads();                     // all reads of this buffer done
        if (c + 2 < 4) issue(c + 2, c & 1);
    }

    // ---- epilogue: regs -> gmem ----
    const int p0loc = p0 - pbase;
    #pragma unroll
    for (int mt = 0; mt < 2; mt++) {
        #pragma unroll
        for (int h = 0; h < 2; h++) {
            int row = wr * 32 + mt * 16 + (lane >> 2) + h * 8;
            if (row < pcnt) {
                int p = p0loc + row;
                int n = p / D;
                int i = p - n * D;
                float* ob = out + (size_t)n * 128 * D + i;
                #pragma unroll
                for (int nt = 0; nt < 8; nt++) {
                    int o = wc * 64 + nt * 8 + (lane & 3) * 2;
                    ob[(size_t)o * D]       = acc[mt * 32 + nt * 4 + h * 2 + 0];
                    ob[(size_t)(o + 1) * D] = acc[mt * 32 + nt * 4 + h * 2 + 1];
                }
            }
        }
    }
}

// ---------------------------------------------------------------------------
__global__ __launch_bounds__(256, 2)
void irreps_mma_kernel(float* __restrict__ out) {
    extern __shared__ char smem[];
    int tile = blockIdx.x;
    if (tile >= g_ntiles) return;

    const int p0   = g_t_p0[tile];
    const int pcnt = g_t_pcnt[tile];
    const int g    = g_t_seg[tile];
    const int ir   = g_t_irr[tile];

    if (ir == 0)        // D=5
        body<5>(out + (size_t)2048 * 128 * 4, smem, p0, pcnt, g, 2, 8192);
    else if (ir == 1)   // D=3
        body<3>(out + (size_t)2048 * 128 * 1, smem, p0, pcnt, g, 1, 2048);
    else                // D=1
        body<1>(out, smem, p0, pcnt, g, 0, 0);
}

// ---------------------------------------------------------------------------
extern "C" void kernel_launch(void* const* d_in, const int* in_sizes, int n_in,
                              void* d_out, int out_size) {
    const float* x0 = (const float*)d_in[0];   // (2048,128,1)
    const float* x1 = (const float*)d_in[1];   // (2048,128,3)
    const float* x2 = (const float*)d_in[2];   // (2048,128,5)
    const float* w  = (const float*)d_in[3];   // (32, 49152)
    const int*   rp = (const int*)d_in[4];     // (32,)
    float* out = (float*)d_out;

    cudaFuncSetAttribute(irreps_mma_kernel,
                         cudaFuncAttributeMaxDynamicSharedMemorySize, SMEM_BYTES);

    prep_kernel<<<481, 256>>>(w, x0, x1, x2, rp);
    irreps_mma_kernel<<<MAX_TILES, 256, SMEM_BYTES>>>(out);
}